// round 15
// baseline (speedup 1.0000x reference)
#include <cuda_runtime.h>
#include <cuda_fp16.h>
#include <cstdint>
#include <cstddef>

// Problem constants
#define TOKENS 32768      // 8 * 4096
#define DIN    1024
#define RNK    64
#define NE     8
#define N72    72         // NE + RNK
#define DOUT   1024
#define KMID   512        // NE * RNK
#define SCALING 0.25f     // alpha / r = 16/64

#define NPREP  16         // weight-prep CTAs (bids 0..15)
#define NMB    256        // number of 128-token m-blocks
#define NTILES 2048       // 256 m-blocks x 8 n-blocks
#define W72_V4 (N72 * DIN / 4)        // 18432
#define WT_V4  (DOUT * KMID / 4)      // 131072

// ---------------------------------------------------------------------------
// Scratch (device globals; zero-initialized at module load; self-resetting)
// ---------------------------------------------------------------------------
__device__ __half g_W72h[N72 * DIN];             // [72][1024] fp16
__device__ __half g_Wt[DOUT * KMID];             // [o][k]: Wt[o][e*64+r] = B[e][o][r]
__device__ __half g_Dh[(size_t)TOKENS * KMID];   // 32 MiB: D[t][e*64+r] fp16
__device__ unsigned g_flag[NMB];                 // per-m-block ready flags
__device__ unsigned g_cnt[NMB];                  // per-m-block consumer completions
__device__ unsigned g_w72;                       // W72h prep completions (0..16)
__device__ unsigned g_wt;                        // Wt prep completions (0..16)
__device__ unsigned g_done;                      // total consumer completions

// ---------------------------------------------------------------------------
// Helpers
// ---------------------------------------------------------------------------
__device__ __forceinline__ void mma16(float c[4], const unsigned a[4],
                                      unsigned b0, unsigned b1) {
    asm volatile(
        "mma.sync.aligned.m16n8k16.row.col.f32.f16.f16.f32 "
        "{%0,%1,%2,%3}, {%4,%5,%6,%7}, {%8,%9}, {%0,%1,%2,%3};\n"
        : "+f"(c[0]), "+f"(c[1]), "+f"(c[2]), "+f"(c[3])
        : "r"(a[0]), "r"(a[1]), "r"(a[2]), "r"(a[3]), "r"(b0), "r"(b1));
}

__device__ __forceinline__ void cp16(void* smem, const void* gmem) {
    unsigned saddr = (unsigned)__cvta_generic_to_shared(smem);
    asm volatile("cp.async.cg.shared.global [%0], [%1], 16;\n"
                 :: "r"(saddr), "l"(gmem));
}

__device__ __forceinline__ uint32_t smem_u32(const void* p) {
    return (uint32_t)__cvta_generic_to_shared(p);
}

__device__ __forceinline__ void ldsm4(unsigned& r0, unsigned& r1,
                                      unsigned& r2, unsigned& r3,
                                      uint32_t addr) {
    asm volatile("ldmatrix.sync.aligned.m8n8.x4.shared.b16 "
                 "{%0,%1,%2,%3}, [%4];"
                 : "=r"(r0), "=r"(r1), "=r"(r2), "=r"(r3) : "r"(addr));
}

__device__ __forceinline__ unsigned ld_acq(const unsigned* p) {
    unsigned v;
    asm volatile("ld.acquire.gpu.global.u32 %0, [%1];"
                 : "=r"(v) : "l"(p) : "memory");
    return v;
}

// ---------------------------------------------------------------------------
// K_MAIN: single launch.
//   bids [0,16):      prep — W72h (signal g_w72), then Wt (signal g_wt)
//   bids [16,272):    producer — spin g_w72, router+compress -> softmax -> D
//   bids [272,2320):  consumer — spin flag[mb] (+g_wt), GEMM2 tile, end-reset
// ---------------------------------------------------------------------------
#define BM 128
#define BN 128
#define NKT 8                               // 512 / 64
#define STG_W (2 * BM * 36)                 // A+B words per stage
#define KM_SMEM (2 * STG_W * 4)             // 73728 B -> 2 CTAs/SM

__global__ __launch_bounds__(256, 2) void k_main(const float* __restrict__ X,
                                                 const float* __restrict__ route_w,
                                                 const float* __restrict__ Aw,
                                                 const float* __restrict__ B,
                                                 float* __restrict__ Y) {
    extern __shared__ char smraw[];
    int tid = threadIdx.x, warp = tid >> 5, lane = tid & 31;
    int bid = blockIdx.x;

    if (bid < NPREP) {
        // ===================== PREP (weights fp16) =====================
        int t = bid * 256 + tid;            // 0..4095
        const int nth = NPREP * 256;

        // W72h: rows 0..7 route_w, 8..71 A
        for (int v = t; v < W72_V4; v += nth) {
            int j = v * 4;
            int n = j >> 10, d = j & 1023;
            const float* src = (n < NE) ? (route_w + (size_t)n * DIN + d)
                                        : (Aw + (size_t)(n - NE) * DIN + d);
            float4 x = *(const float4*)src;
            __half2* dst = (__half2*)(g_W72h + j);
            dst[0] = __floats2half2_rn(x.x, x.y);
            dst[1] = __floats2half2_rn(x.z, x.w);
        }
        __threadfence();
        __syncthreads();
        if (tid == 0) atomicAdd(&g_w72, 1u);

        // Wt[o][e*64+r] = B[e][o][r]
        for (int v = t; v < WT_V4; v += nth) {
            int j = v * 4;
            int o = j >> 9, k = j & 511;
            int e = k >> 6, r = k & 63;
            float4 x = *(const float4*)(B + (size_t)(e * DOUT + o) * RNK + r);
            __half2* dst = (__half2*)(g_Wt + j);
            dst[0] = __floats2half2_rn(x.x, x.y);
            dst[1] = __floats2half2_rn(x.z, x.w);
        }
        __threadfence();
        __syncthreads();
        if (tid == 0) atomicAdd(&g_wt, 1u);
        return;
    }

    if (bid < NPREP + NMB) {
        // ===================== PRODUCER (k1 body) =====================
        int mb = bid - NPREP;
        int m0 = mb * 128;

        // wait for W72h prep (resolves ~0.5us after launch)
        if (tid == 0) {
            while (ld_acq(&g_w72) < NPREP) __nanosleep(100);
        }
        __syncthreads();

        unsigned* Xs = (unsigned*)smraw;             // [128][36] words
        unsigned* Ws = (unsigned*)smraw + 128 * 36;  // [72][36] words

        float acc[9][4] = {};
        float4 xr[8];
        uint4  wr[3];

        auto loadg = [&](int kt) {
            #pragma unroll
            for (int i = 0; i < 8; i++) {
                int idx = tid + i * 256;
                int r = idx >> 4, c4 = idx & 15;
                xr[i] = *(const float4*)(X + (size_t)(m0 + r) * DIN + kt + c4 * 4);
            }
            #pragma unroll
            for (int i = 0; i < 3; i++) {
                int idx = tid + i * 256;
                if (idx < 576) {
                    int r = idx >> 3, c = idx & 7;
                    wr[i] = *(const uint4*)((const char*)(g_W72h + r * DIN + kt) + c * 16);
                }
            }
        };

        loadg(0);

        for (int kt = 0; kt < 16; kt++) {
            #pragma unroll
            for (int i = 0; i < 8; i++) {
                int idx = tid + i * 256;
                int r = idx >> 4, c4 = idx & 15;
                __half2* dst = (__half2*)(Xs + r * 36 + c4 * 2);
                dst[0] = __floats2half2_rn(xr[i].x, xr[i].y);
                dst[1] = __floats2half2_rn(xr[i].z, xr[i].w);
            }
            #pragma unroll
            for (int i = 0; i < 3; i++) {
                int idx = tid + i * 256;
                if (idx < 576) {
                    int r = idx >> 3, c = idx & 7;
                    *(uint4*)(Ws + r * 36 + c * 4) = wr[i];
                }
            }
            __syncthreads();

            if (kt + 1 < 16) loadg((kt + 1) * 64);

            #pragma unroll
            for (int s = 0; s < 4; s++) {
                unsigned a[4];
                int ar = warp * 16 + (lane >> 2);
                int w = s * 8 + (lane & 3);
                a[0] = Xs[ar * 36 + w];
                a[1] = Xs[(ar + 8) * 36 + w];
                a[2] = Xs[ar * 36 + w + 4];
                a[3] = Xs[(ar + 8) * 36 + w + 4];
                #pragma unroll
                for (int j = 0; j < 9; j++) {
                    int br = j * 8 + (lane >> 2);
                    unsigned b0 = Ws[br * 36 + w];
                    unsigned b1 = Ws[br * 36 + w + 4];
                    mma16(acc[j], a, b0, b1);
                }
            }
            __syncthreads();
        }

        // stage C72 into smem: Cs[128][76]
        float* Cs = (float*)smraw;
        #pragma unroll
        for (int j = 0; j < 9; j++) {
            int col = j * 8 + 2 * (lane & 3);
            int row = warp * 16 + (lane >> 2);
            Cs[row * 76 + col]           = acc[j][0];
            Cs[row * 76 + col + 1]       = acc[j][1];
            Cs[(row + 8) * 76 + col]     = acc[j][2];
            Cs[(row + 8) * 76 + col + 1] = acc[j][3];
        }
        __syncthreads();

        // softmax + outer product -> g_Dh
        int grp = tid >> 3, g = tid & 7;
        #pragma unroll
        for (int tt = 0; tt < 4; tt++) {
            int lt = grp + tt * 32;
            const float* crow = Cs + lt * 76;
            float mx = crow[0];
            #pragma unroll
            for (int e = 1; e < 8; e++) mx = fmaxf(mx, crow[e]);
            float p[8]; float se = 0.f;
            #pragma unroll
            for (int e = 0; e < 8; e++) { p[e] = expf(crow[e] - mx); se += p[e]; }
            float inv = 1.f / se;
            __half* drow = g_Dh + (size_t)(m0 + lt) * KMID;
            #pragma unroll
            for (int e = 0; e < 8; e++) {
                float route = p[e] * inv;
                #pragma unroll
                for (int h = 0; h < 2; h++) {
                    int r = (g + h * 8) * 4;
                    float4 cv = *(const float4*)(crow + 8 + r);
                    __half2 h0 = __floats2half2_rn(route * cv.x, route * cv.y);
                    __half2 h1 = __floats2half2_rn(route * cv.z, route * cv.w);
                    *(__half2*)(drow + e * 64 + r)     = h0;
                    *(__half2*)(drow + e * 64 + r + 2) = h1;
                }
            }
        }

        // publish: all stores globally visible, then release flag
        __threadfence();
        __syncthreads();
        if (tid == 0) {
            asm volatile("st.release.gpu.global.u32 [%0], %1;"
                         :: "l"(&g_flag[mb]), "r"(1u) : "memory");
        }
        return;
    }

    // ===================== CONSUMER (GEMM2 tile) =====================
    {
        int q = bid - (NPREP + NMB);
        int mb = q >> 3;                 // m-block index (low m first)
        int nb = q & 7;
        int m0 = mb * BM, n0 = nb * BN;

        // spin until producer mb done (Wt prep finishes far earlier; check once)
        if (tid == 0) {
            while (!ld_acq(&g_flag[mb])) __nanosleep(200);
            while (ld_acq(&g_wt) < NPREP) __nanosleep(100);
        }
        __syncthreads();

        unsigned* sh = (unsigned*)smraw;
        int wm = warp >> 2, wn = warp & 3;   // 2x4 warps, warp tile 64x32

        unsigned* stA[2] = { sh, sh + STG_W };
        unsigned* stB[2] = { sh + BM * 36, sh + STG_W + BM * 36 };

        int g4 = lane >> 3, lr = lane & 7;
        uint32_t relA[4], relB[2];
        {
            int rowSel = (g4 & 1) * 8 + lr;
            int wordSel = (g4 >> 1) * 4;
            #pragma unroll
            for (int mt = 0; mt < 4; mt++)
                relA[mt] = ((wm * 64 + mt * 16 + rowSel) * 36 + wordSel) * 4;
            int browSel = (g4 >> 1) * 8 + lr;
            int bwordSel = (g4 & 1) * 4;
            #pragma unroll
            for (int np = 0; np < 2; np++)
                relB[np] = ((wn * 32 + np * 16 + browSel) * 36 + bwordSel) * 4;
        }
        uint32_t uA[2] = { smem_u32(stA[0]), smem_u32(stA[1]) };
        uint32_t uB[2] = { smem_u32(stB[0]), smem_u32(stB[1]) };

        auto prefetch = [&](int st, int kt) {
            unsigned* As = stA[st];
            unsigned* Bs = stB[st];
            const __half* gA = g_Dh + (size_t)m0 * KMID + kt * 64;
            const __half* gB = g_Wt + (size_t)n0 * KMID + kt * 64;
            #pragma unroll
            for (int i = 0; i < 4; i++) {
                int j = tid + i * 256;
                int r = j >> 3, c = j & 7;
                cp16(As + r * 36 + c * 4, (const char*)(gA + (size_t)r * KMID) + c * 16);
            }
            #pragma unroll
            for (int i = 0; i < 4; i++) {
                int j = tid + i * 256;
                int r = j >> 3, c = j & 7;
                cp16(Bs + r * 36 + c * 4, (const char*)(gB + (size_t)r * KMID) + c * 16);
            }
            asm volatile("cp.async.commit_group;\n" ::: "memory");
        };

        float acc[4][4][4] = {};

        prefetch(0, 0);

        for (int kt = 0; kt < NKT; kt++) {
            int st = kt & 1;
            if (kt + 1 < NKT) {
                prefetch(st ^ 1, kt + 1);
                asm volatile("cp.async.wait_group 1;\n" ::: "memory");
            } else {
                asm volatile("cp.async.wait_group 0;\n" ::: "memory");
            }
            __syncthreads();

            #pragma unroll
            for (int s = 0; s < 4; s++) {
                unsigned a[4][4], b[2][4];
                #pragma unroll
                for (int mt = 0; mt < 4; mt++)
                    ldsm4(a[mt][0], a[mt][1], a[mt][2], a[mt][3],
                          uA[st] + relA[mt] + s * 32);
                #pragma unroll
                for (int np = 0; np < 2; np++)
                    ldsm4(b[np][0], b[np][1], b[np][2], b[np][3],
                          uB[st] + relB[np] + s * 32);
                #pragma unroll
                for (int mt = 0; mt < 4; mt++) {
                    #pragma unroll
                    for (int np = 0; np < 2; np++) {
                        mma16(acc[mt][np * 2],     a[mt], b[np][0], b[np][1]);
                        mma16(acc[mt][np * 2 + 1], a[mt], b[np][2], b[np][3]);
                    }
                }
            }
            __syncthreads();
        }

        // epilogue
        #pragma unroll
        for (int mt = 0; mt < 4; mt++) {
            #pragma unroll
            for (int nt = 0; nt < 4; nt++) {
                int row = m0 + wm * 64 + mt * 16 + (lane >> 2);
                int col = n0 + wn * 32 + nt * 8 + 2 * (lane & 3);
                float2 v0 = make_float2(acc[mt][nt][0] * SCALING,
                                        acc[mt][nt][1] * SCALING);
                float2 v1 = make_float2(acc[mt][nt][2] * SCALING,
                                        acc[mt][nt][3] * SCALING);
                *(float2*)(Y + (size_t)row * DOUT + col)       = v0;
                *(float2*)(Y + (size_t)(row + 8) * DOUT + col) = v1;
            }
        }

        // ---------- self-reset of sync state (graph-replay safe) ----------
        __syncthreads();
        if (tid == 0) {
            unsigned prev = atomicAdd(&g_cnt[mb], 1u);
            if (prev == 7u) {                 // 8th consumer of this mb
                g_cnt[mb] = 0u;
                g_flag[mb] = 0u;
            }
            unsigned d = atomicAdd(&g_done, 1u);
            if (d == NTILES - 1u) {           // globally last consumer
                g_done = 0u;
                g_w72 = 0u;
                g_wt = 0u;
            }
        }
    }
}

// ---------------------------------------------------------------------------
// Launch
// ---------------------------------------------------------------------------
extern "C" void kernel_launch(void* const* d_in, const int* in_sizes, int n_in,
                              void* d_out, int out_size) {
    (void)in_sizes; (void)n_in; (void)out_size;
    const float* x       = (const float*)d_in[0];
    const float* route_w = (const float*)d_in[1];
    const float* A       = (const float*)d_in[2];
    const float* B       = (const float*)d_in[3];
    float* y = (float*)d_out;

    cudaFuncSetAttribute(k_main, cudaFuncAttributeMaxDynamicSharedMemorySize,
                         KM_SMEM);

    k_main<<<NPREP + NMB + NTILES, 256, KM_SMEM>>>(x, route_w, A, B, y);
}

// round 16
// speedup vs baseline: 1.0400x; 1.0400x over previous
#include <cuda_runtime.h>
#include <cuda_fp16.h>
#include <cstdint>
#include <cstddef>

// Problem constants
#define TOKENS 32768      // 8 * 4096
#define DIN    1024
#define RNK    64
#define NE     8
#define N72    72         // NE + RNK
#define DOUT   1024
#define KMID   512        // NE * RNK
#define SCALING 0.25f     // alpha / r = 16/64 (folded into g_Wt; exact pow2)

#define NMB    256        // number of 128-token m-blocks

// ---------------------------------------------------------------------------
// Scratch (device globals)
// ---------------------------------------------------------------------------
__device__ __half g_W72h[N72 * DIN];             // [72][1024] fp16
__device__ __half g_Wt[DOUT * KMID];             // [o][k]: 0.25*B[e][o][r]
__device__ __half g_Dh[(size_t)TOKENS * KMID];   // 32 MiB: D[t][e*64+r] fp16
__device__ unsigned g_flag[NMB];                 // per-m-block ready flags

// ---------------------------------------------------------------------------
// Helpers
// ---------------------------------------------------------------------------
__device__ __forceinline__ void mma16(float c[4], const unsigned a[4],
                                      unsigned b0, unsigned b1) {
    asm volatile(
        "mma.sync.aligned.m16n8k16.row.col.f32.f16.f16.f32 "
        "{%0,%1,%2,%3}, {%4,%5,%6,%7}, {%8,%9}, {%0,%1,%2,%3};\n"
        : "+f"(c[0]), "+f"(c[1]), "+f"(c[2]), "+f"(c[3])
        : "r"(a[0]), "r"(a[1]), "r"(a[2]), "r"(a[3]), "r"(b0), "r"(b1));
}

__device__ __forceinline__ void cp16(void* smem, const void* gmem) {
    unsigned saddr = (unsigned)__cvta_generic_to_shared(smem);
    asm volatile("cp.async.cg.shared.global [%0], [%1], 16;\n"
                 :: "r"(saddr), "l"(gmem));
}

__device__ __forceinline__ uint32_t smem_u32(const void* p) {
    return (uint32_t)__cvta_generic_to_shared(p);
}

__device__ __forceinline__ void ldsm4(unsigned& r0, unsigned& r1,
                                      unsigned& r2, unsigned& r3,
                                      uint32_t addr) {
    asm volatile("ldmatrix.sync.aligned.m8n8.x4.shared.b16 "
                 "{%0,%1,%2,%3}, [%4];"
                 : "=r"(r0), "=r"(r1), "=r"(r2), "=r"(r3) : "r"(addr));
}

// ---------------------------------------------------------------------------
// K0: prep weights (fp16) + reset flags — grid-stride, vectorized.
// SCALING folded into Wt (power-of-2 => bit-exact vs epilogue multiply).
// ---------------------------------------------------------------------------
#define K0_THREADS 512
#define K0_BLOCKS  148
#define W72_V4 (N72 * DIN / 4)        // 18432
#define WT_V4  (DOUT * KMID / 4)      // 131072

__global__ __launch_bounds__(K0_THREADS) void k0_prep(
        const float* __restrict__ route_w,
        const float* __restrict__ A,
        const float* __restrict__ B) {
    int t = blockIdx.x * K0_THREADS + threadIdx.x;
    int nth = K0_BLOCKS * K0_THREADS;

    for (int i = t; i < NMB; i += nth) g_flag[i] = 0;

    // W72h: rows 0..7 route_w, 8..71 A
    for (int v = t; v < W72_V4; v += nth) {
        int j = v * 4;
        int n = j >> 10, d = j & 1023;
        const float* src = (n < NE) ? (route_w + (size_t)n * DIN + d)
                                    : (A + (size_t)(n - NE) * DIN + d);
        float4 x = *(const float4*)src;
        __half2* dst = (__half2*)(g_W72h + j);
        dst[0] = __floats2half2_rn(x.x, x.y);
        dst[1] = __floats2half2_rn(x.z, x.w);
    }

    // Wt[o][e*64+r] = SCALING * B[e][o][r]
    for (int v = t; v < WT_V4; v += nth) {
        int j = v * 4;
        int o = j >> 9, k = j & 511;
        int e = k >> 6, r = k & 63;
        float4 x = *(const float4*)(B + (size_t)(e * DOUT + o) * RNK + r);
        __half2* dst = (__half2*)(g_Wt + j);
        dst[0] = __floats2half2_rn(x.x * SCALING, x.y * SCALING);
        dst[1] = __floats2half2_rn(x.z * SCALING, x.w * SCALING);
    }
}

// ---------------------------------------------------------------------------
// K_MAIN: producer/consumer grid (one tile per CTA, grid = 256 + 2048).
//   bids [0,256):   producer — router+compress -> softmax -> D (gmem) -> flag
//   bids [256,2304): consumer — GEMM2 tile (m = q>>3, n = q&7); B prefetched
//                    before the flag spin (Wt ready since k0).
// Consumer: 8 warps (2x4), warp tile 64x32, 2-stage cp.async ring, ldmatrix.
// ---------------------------------------------------------------------------
#define BM 128
#define BN 128
#define NKT 8                               // 512 / 64
#define STG_W (2 * BM * 36)                 // A+B words per stage
#define KM_SMEM (2 * STG_W * 4)             // 73728 B -> 2 CTAs/SM

__global__ __launch_bounds__(256, 2) void k_main(const float* __restrict__ X,
                                                 float* __restrict__ Y) {
    extern __shared__ char smraw[];
    int tid = threadIdx.x, warp = tid >> 5, lane = tid & 31;
    int bid = blockIdx.x;

    if (bid < NMB) {
        // ===================== PRODUCER (k1 body) =====================
        int m0 = bid * 128;
        unsigned* Xs = (unsigned*)smraw;             // [128][36] words
        unsigned* Ws = (unsigned*)smraw + 128 * 36;  // [72][36] words

        float acc[9][4] = {};
        float4 xr[8];
        uint4  wr[3];

        auto loadg = [&](int kt) {
            #pragma unroll
            for (int i = 0; i < 8; i++) {
                int idx = tid + i * 256;
                int r = idx >> 4, c4 = idx & 15;
                xr[i] = *(const float4*)(X + (size_t)(m0 + r) * DIN + kt + c4 * 4);
            }
            #pragma unroll
            for (int i = 0; i < 3; i++) {
                int idx = tid + i * 256;
                if (idx < 576) {
                    int r = idx >> 3, c = idx & 7;
                    wr[i] = *(const uint4*)((const char*)(g_W72h + r * DIN + kt) + c * 16);
                }
            }
        };

        loadg(0);

        for (int kt = 0; kt < 16; kt++) {
            #pragma unroll
            for (int i = 0; i < 8; i++) {
                int idx = tid + i * 256;
                int r = idx >> 4, c4 = idx & 15;
                __half2* dst = (__half2*)(Xs + r * 36 + c4 * 2);
                dst[0] = __floats2half2_rn(xr[i].x, xr[i].y);
                dst[1] = __floats2half2_rn(xr[i].z, xr[i].w);
            }
            #pragma unroll
            for (int i = 0; i < 3; i++) {
                int idx = tid + i * 256;
                if (idx < 576) {
                    int r = idx >> 3, c = idx & 7;
                    *(uint4*)(Ws + r * 36 + c * 4) = wr[i];
                }
            }
            __syncthreads();

            if (kt + 1 < 16) loadg((kt + 1) * 64);

            #pragma unroll
            for (int s = 0; s < 4; s++) {
                unsigned a[4];
                int ar = warp * 16 + (lane >> 2);
                int w = s * 8 + (lane & 3);
                a[0] = Xs[ar * 36 + w];
                a[1] = Xs[(ar + 8) * 36 + w];
                a[2] = Xs[ar * 36 + w + 4];
                a[3] = Xs[(ar + 8) * 36 + w + 4];
                #pragma unroll
                for (int j = 0; j < 9; j++) {
                    int br = j * 8 + (lane >> 2);
                    unsigned b0 = Ws[br * 36 + w];
                    unsigned b1 = Ws[br * 36 + w + 4];
                    mma16(acc[j], a, b0, b1);
                }
            }
            __syncthreads();
        }

        // stage C72 into smem: Cs[128][76]
        float* Cs = (float*)smraw;
        #pragma unroll
        for (int j = 0; j < 9; j++) {
            int col = j * 8 + 2 * (lane & 3);
            int row = warp * 16 + (lane >> 2);
            Cs[row * 76 + col]           = acc[j][0];
            Cs[row * 76 + col + 1]       = acc[j][1];
            Cs[(row + 8) * 76 + col]     = acc[j][2];
            Cs[(row + 8) * 76 + col + 1] = acc[j][3];
        }
        __syncthreads();

        // softmax + outer product -> g_Dh
        int grp = tid >> 3, g = tid & 7;
        #pragma unroll
        for (int tt = 0; tt < 4; tt++) {
            int lt = grp + tt * 32;
            const float* crow = Cs + lt * 76;
            float mx = crow[0];
            #pragma unroll
            for (int e = 1; e < 8; e++) mx = fmaxf(mx, crow[e]);
            float p[8]; float se = 0.f;
            #pragma unroll
            for (int e = 0; e < 8; e++) { p[e] = expf(crow[e] - mx); se += p[e]; }
            float inv = 1.f / se;
            __half* drow = g_Dh + (size_t)(m0 + lt) * KMID;
            #pragma unroll
            for (int e = 0; e < 8; e++) {
                float route = p[e] * inv;
                #pragma unroll
                for (int h = 0; h < 2; h++) {
                    int r = (g + h * 8) * 4;
                    float4 cv = *(const float4*)(crow + 8 + r);
                    __half2 h0 = __floats2half2_rn(route * cv.x, route * cv.y);
                    __half2 h1 = __floats2half2_rn(route * cv.z, route * cv.w);
                    *(__half2*)(drow + e * 64 + r)     = h0;
                    *(__half2*)(drow + e * 64 + r + 2) = h1;
                }
            }
        }

        // publish: all stores globally visible, then release flag
        __threadfence();
        __syncthreads();
        if (tid == 0) {
            asm volatile("st.release.gpu.global.u32 [%0], %1;"
                         :: "l"(&g_flag[bid]), "r"(1u) : "memory");
        }
        return;
    }

    // ===================== CONSUMER (GEMM2 tile) =====================
    {
        int q = bid - NMB;
        int mb = q >> 3;                 // m-block index (low m first)
        int nb = q & 7;
        int m0 = mb * BM, n0 = nb * BN;

        unsigned* sh = (unsigned*)smraw;
        int wm = warp >> 2, wn = warp & 3;   // 2x4 warps, warp tile 64x32

        unsigned* stA[2] = { sh, sh + STG_W };
        unsigned* stB[2] = { sh + BM * 36, sh + STG_W + BM * 36 };

        int g4 = lane >> 3, lr = lane & 7;
        uint32_t relA[4], relB[2];
        {
            int rowSel = (g4 & 1) * 8 + lr;
            int wordSel = (g4 >> 1) * 4;
            #pragma unroll
            for (int mt = 0; mt < 4; mt++)
                relA[mt] = ((wm * 64 + mt * 16 + rowSel) * 36 + wordSel) * 4;
            int browSel = (g4 >> 1) * 8 + lr;
            int bwordSel = (g4 & 1) * 4;
            #pragma unroll
            for (int np = 0; np < 2; np++)
                relB[np] = ((wn * 32 + np * 16 + browSel) * 36 + bwordSel) * 4;
        }
        uint32_t uA[2] = { smem_u32(stA[0]), smem_u32(stA[1]) };
        uint32_t uB[2] = { smem_u32(stB[0]), smem_u32(stB[1]) };

        auto prefB = [&](int st, int kt) {
            unsigned* Bs = stB[st];
            const __half* gB = g_Wt + (size_t)n0 * KMID + kt * 64;
            #pragma unroll
            for (int i = 0; i < 4; i++) {
                int j = tid + i * 256;
                int r = j >> 3, c = j & 7;
                cp16(Bs + r * 36 + c * 4, (const char*)(gB + (size_t)r * KMID) + c * 16);
            }
        };
        auto prefA = [&](int st, int kt) {
            unsigned* As = stA[st];
            const __half* gA = g_Dh + (size_t)m0 * KMID + kt * 64;
            #pragma unroll
            for (int i = 0; i < 4; i++) {
                int j = tid + i * 256;
                int r = j >> 3, c = j & 7;
                cp16(As + r * 36 + c * 4, (const char*)(gA + (size_t)r * KMID) + c * 16);
            }
        };

        // B depends only on Wt (ready before this launch): prefetch stage-0 B
        // BEFORE spinning on the producer flag.
        prefB(0, 0);

        // spin until producer mb done
        if (tid == 0) {
            unsigned v = 0;
            while (true) {
                asm volatile("ld.acquire.gpu.global.u32 %0, [%1];"
                             : "=r"(v) : "l"(&g_flag[mb]) : "memory");
                if (v) break;
                __nanosleep(200);
            }
        }
        __syncthreads();

        float acc[4][4][4] = {};

        prefA(0, 0);
        asm volatile("cp.async.commit_group;\n" ::: "memory");

        for (int kt = 0; kt < NKT; kt++) {
            int st = kt & 1;
            if (kt + 1 < NKT) {
                prefA(st ^ 1, kt + 1);
                prefB(st ^ 1, kt + 1);
                asm volatile("cp.async.commit_group;\n" ::: "memory");
                asm volatile("cp.async.wait_group 1;\n" ::: "memory");
            } else {
                asm volatile("cp.async.wait_group 0;\n" ::: "memory");
            }
            __syncthreads();

            #pragma unroll
            for (int s = 0; s < 4; s++) {
                unsigned a[4][4], b[2][4];
                #pragma unroll
                for (int mt = 0; mt < 4; mt++)
                    ldsm4(a[mt][0], a[mt][1], a[mt][2], a[mt][3],
                          uA[st] + relA[mt] + s * 32);
                #pragma unroll
                for (int np = 0; np < 2; np++)
                    ldsm4(b[np][0], b[np][1], b[np][2], b[np][3],
                          uB[st] + relB[np] + s * 32);
                #pragma unroll
                for (int mt = 0; mt < 4; mt++) {
                    #pragma unroll
                    for (int np = 0; np < 2; np++) {
                        mma16(acc[mt][np * 2],     a[mt], b[np][0], b[np][1]);
                        mma16(acc[mt][np * 2 + 1], a[mt], b[np][2], b[np][3]);
                    }
                }
            }
            __syncthreads();
        }

        // epilogue (scaling already folded into Wt)
        #pragma unroll
        for (int mt = 0; mt < 4; mt++) {
            #pragma unroll
            for (int nt = 0; nt < 4; nt++) {
                int row = m0 + wm * 64 + mt * 16 + (lane >> 2);
                int col = n0 + wn * 32 + nt * 8 + 2 * (lane & 3);
                float2 v0 = make_float2(acc[mt][nt][0], acc[mt][nt][1]);
                float2 v1 = make_float2(acc[mt][nt][2], acc[mt][nt][3]);
                *(float2*)(Y + (size_t)row * DOUT + col)       = v0;
                *(float2*)(Y + (size_t)(row + 8) * DOUT + col) = v1;
            }
        }
    }
}

// ---------------------------------------------------------------------------
// Launch
// ---------------------------------------------------------------------------
extern "C" void kernel_launch(void* const* d_in, const int* in_sizes, int n_in,
                              void* d_out, int out_size) {
    (void)in_sizes; (void)n_in; (void)out_size;
    const float* x       = (const float*)d_in[0];
    const float* route_w = (const float*)d_in[1];
    const float* A       = (const float*)d_in[2];
    const float* B       = (const float*)d_in[3];
    float* y = (float*)d_out;

    cudaFuncSetAttribute(k_main, cudaFuncAttributeMaxDynamicSharedMemorySize,
                         KM_SMEM);

    k0_prep<<<K0_BLOCKS, K0_THREADS>>>(route_w, A, B);
    k_main<<<NMB + NMB * 8, 256, KM_SMEM>>>(x, y);
}